// round 2
// baseline (speedup 1.0000x reference)
#include <cuda_runtime.h>
#include <cstdint>

#define DI __device__ __forceinline__

// ---------------- problem constants ----------------
constexpr int B_   = 16;
constexpr int C_   = 384;
constexpr int H_   = 56;
constexpr int W_   = 56;
constexpr int HW   = H_ * W_;          // 3136
constexpr int M_   = B_ * HW;          // 50176 (pixels)
constexpr int K0   = 2 * C_;           // 768
constexpr int NOUT = 384;

// ---------------- device scratch ----------------
__device__ __align__(256) float g_xj[(size_t)B_ * C_ * HW];   // 77 MB
__device__ __align__(256) float g_Wr[NOUT * K0];              // tf32-rounded weights

// ---------------- PTX helpers ----------------
DI uint32_t smem_u32(const void* p) {
    uint32_t a;
    asm("{ .reg .u64 t; cvta.to.shared.u64 t, %1; cvt.u32.u64 %0, t; }"
        : "=r"(a) : "l"(p));
    return a;
}

DI uint32_t f2tf32(float f) {
    uint32_t r;
    asm("cvt.rna.tf32.f32 %0, %1;" : "=r"(r) : "f"(f));
    return r;
}

#define CP_ASYNC16(smem, gptr) \
    asm volatile("cp.async.cg.shared.global [%0], [%1], 16;" :: "r"(smem), "l"(gptr))
#define CP_COMMIT() asm volatile("cp.async.commit_group;")
#define CP_WAIT1()  asm volatile("cp.async.wait_group 1;")
#define CP_WAIT0()  asm volatile("cp.async.wait_group 0;")

DI void ldsm_x4(uint32_t* r, uint32_t addr) {
    asm volatile("ldmatrix.sync.aligned.m8n8.x4.shared.b16 {%0,%1,%2,%3}, [%4];"
                 : "=r"(r[0]), "=r"(r[1]), "=r"(r[2]), "=r"(r[3]) : "r"(addr));
}

DI float lds_f32(uint32_t addr) {
    float f;
    asm volatile("ld.shared.f32 %0, [%1];" : "=f"(f) : "r"(addr));
    return f;
}

// D[16 n_out][8 pix] += A[16 n_out][8 k] * B[8 k][8 pix]
DI void mma_tf32(float* d, const uint32_t* a, uint32_t b0, uint32_t b1) {
    asm volatile(
        "mma.sync.aligned.m16n8k8.row.col.f32.tf32.tf32.f32 "
        "{%0,%1,%2,%3},{%4,%5,%6,%7},{%8,%9},{%0,%1,%2,%3};"
        : "+f"(d[0]), "+f"(d[1]), "+f"(d[2]), "+f"(d[3])
        : "r"(a[0]), "r"(a[1]), "r"(a[2]), "r"(a[3]), "r"(b0), "r"(b1));
}

// ---------------- kernel 1: x_j (log-shift-max) ----------------
__global__ void xj_kernel(const float* __restrict__ x) {
    __shared__ float tile[HW];
    const int img = blockIdx.x;                      // b*C + c
    const float* src = x + (size_t)img * HW;
    for (int i = threadIdx.x; i < HW; i += blockDim.x) tile[i] = src[i];
    __syncthreads();
    for (int p = threadIdx.x; p < HW; p += blockDim.x) {
        const int h = p / W_, w = p % W_;
        const float v = tile[p];
        float mj = 0.f;
        const int shifts[5] = {1, 3, 7, 15, 31};
#pragma unroll
        for (int si = 0; si < 5; si++) {
            const int s = shifts[si];
            int hm = h - s; if (hm < 0)   hm += H_;
            int hp = h + s; if (hp >= H_) hp -= H_;
            int wm = w - s; if (wm < 0)   wm += W_;
            int wp = w + s; if (wp >= W_) wp -= W_;
            mj = fmaxf(mj, v - tile[hm * W_ + w]);
            mj = fmaxf(mj, v - tile[hp * W_ + w]);
            mj = fmaxf(mj, v - tile[h * W_ + wm]);
            mj = fmaxf(mj, v - tile[h * W_ + wp]);
        }
        g_xj[(size_t)img * HW + p] = mj;
    }
}

// ---------------- kernel 2: round W to tf32 (RN) ----------------
__global__ void wround_kernel(const float* __restrict__ w) {
    const int i = blockIdx.x * blockDim.x + threadIdx.x;
    if (i < NOUT * K0) g_Wr[i] = __uint_as_float(f2tf32(w[i]));
}

// ---------------- kernel 3: tf32 mma.sync GEMM + BN + GELU ----------------
// D[n_out][pix] ; CTA tile: 128 n_out x 128 pix ; K chunks of 32.
// smem: sW [n][k] (k-contig, pad to 36 words/row, for ldmatrix A-fragments)
//       sX [k][m] (m-contig, pad to 136 words/row, straight cp.async copy)
constexpr int MT  = 128;   // pixels
constexpr int NT  = 128;   // n_out
constexpr int KT  = 32;
constexpr int NCH = K0 / KT;   // 24
constexpr int SXS = 136;       // sX row stride (words)
constexpr int SWS = 36;        // sW row stride (words)
constexpr int SX_STAGE = KT * SXS;   // 4352 words
constexpr int SW_STAGE = NT * SWS;   // 4608 words
constexpr int SMEM_BYTES = (2 * SX_STAGE + 2 * SW_STAGE) * 4;  // 71680

__global__ void __launch_bounds__(256, 2) gemm_kernel(
    const float* __restrict__ x,
    const float* __restrict__ conv_b,
    const float* __restrict__ bn_scale, const float* __restrict__ bn_bias,
    const float* __restrict__ bn_mean,  const float* __restrict__ bn_var,
    float* __restrict__ out)
{
    extern __shared__ float sm[];
    float* sX = sm;                     // [2][KT][SXS]
    float* sW = sm + 2 * SX_STAGE;      // [2][NT][SWS]
    __shared__ float s_s[NT], s_t[NT];

    const int tid  = threadIdx.x;
    const int lane = tid & 31;
    const int wid  = tid >> 5;
    const int wn   = wid & 3;           // n_out warp row (4 x 32)
    const int wp   = wid >> 2;          // pixel warp col (2 x 64)
    const int n0   = blockIdx.x * NT;
    const int m0   = blockIdx.y * MT;

    // fold conv bias + BN:  y = dot * s + t
    if (tid < NT) {
        const int n = n0 + tid;
        const float inv = rsqrtf(bn_var[n] + 1e-5f);
        const float s = inv * bn_scale[n];
        s_s[tid] = s;
        s_t[tid] = (conv_b[n] - bn_mean[n]) * s + bn_bias[n];
    }

    const uint32_t sxB = smem_u32(sX);
    const uint32_t swB = smem_u32(sW);

    // ---- staging ----
    auto load_chunk = [&](int ch, int st) {
        const int kc = ch * KT;
        const uint32_t xb = sxB + (uint32_t)st * SX_STAGE * 4;
        const uint32_t wb = swB + (uint32_t)st * SW_STAGE * 4;
        // sX: 32 k-rows x 128 floats ; 1024 float4s
#pragma unroll
        for (int i = 0; i < 4; i++) {
            const int idx = tid + 256 * i;
            const int k   = idx >> 5;          // 0..31
            const int mv  = idx & 31;          // float4 index along m
            const int m   = m0 + 4 * mv;
            const unsigned b  = (unsigned)m / HW;
            const unsigned hw = (unsigned)m - b * HW;
            const int kg = kc + k;
            const float* src = (kg < C_)
                ? (x    + ((size_t)(b * C_ + kg)      ) * HW + hw)
                : (g_xj + ((size_t)(b * C_ + kg - C_) ) * HW + hw);
            CP_ASYNC16(xb + (uint32_t)(k * SXS + 4 * mv) * 4, src);
        }
        // sW: 128 n-rows x 32 floats ; 1024 float4s
#pragma unroll
        for (int i = 0; i < 4; i++) {
            const int idx = tid + 256 * i;
            const int n   = idx >> 3;          // 0..127
            const int kv  = idx & 7;
            const float* src = g_Wr + (size_t)(n0 + n) * K0 + kc + 4 * kv;
            CP_ASYNC16(wb + (uint32_t)(n * SWS + 4 * kv) * 4, src);
        }
    };

    float acc[2][8][4];
#pragma unroll
    for (int a = 0; a < 2; a++)
#pragma unroll
        for (int j = 0; j < 8; j++)
#pragma unroll
            for (int q = 0; q < 4; q++) acc[a][j][q] = 0.f;

    load_chunk(0, 0);
    CP_COMMIT();

#pragma unroll 1
    for (int ch = 0; ch < NCH; ch++) {
        if (ch + 1 < NCH) {
            load_chunk(ch + 1, (ch + 1) & 1);
            CP_COMMIT();
            CP_WAIT1();
        } else {
            CP_WAIT0();
        }
        __syncthreads();

        const int st = ch & 1;
        const uint32_t xb = sxB + (uint32_t)st * SX_STAGE * 4;
        const uint32_t wb = swB + (uint32_t)st * SW_STAGE * 4;

        // ldmatrix address pieces (per-thread, constant across ksteps except k8)
        const int jrow = (lane & 7) + ((lane >> 3) & 1) * 8;   // row within 16
        const int kcol = ((lane >> 3) >> 1) * 4;               // word offset 0 or 4

#pragma unroll
        for (int ks = 0; ks < 4; ks++) {
            const int k8 = ks * 8;
            uint32_t afr[2][4];
#pragma unroll
            for (int nf = 0; nf < 2; nf++) {
                const int row = wn * 32 + nf * 16 + jrow;
                ldsm_x4(afr[nf], wb + (uint32_t)(row * SWS + k8 + kcol) * 4);
            }
            const uint32_t b0base = xb + (uint32_t)((k8 + (lane & 3)) * SXS
                                                    + wp * 64 + (lane >> 2)) * 4;
#pragma unroll
            for (int j = 0; j < 8; j++) {
                const uint32_t a0 = b0base + (uint32_t)(j * 8) * 4;
                const uint32_t b0 = f2tf32(lds_f32(a0));
                const uint32_t b1 = f2tf32(lds_f32(a0 + (uint32_t)(4 * SXS) * 4));
                mma_tf32(acc[0][j], afr[0], b0, b1);
                mma_tf32(acc[1][j], afr[1], b0, b1);
            }
        }
        __syncthreads();
    }

    // ---- epilogue: BN + exact GELU, write out[b][n][hw] ----
#pragma unroll
    for (int nf = 0; nf < 2; nf++) {
#pragma unroll
        for (int half = 0; half < 2; half++) {
            const int ntile = wn * 32 + nf * 16 + (lane >> 2) + half * 8;
            const int n = n0 + ntile;
            const float s = s_s[ntile];
            const float t = s_t[ntile];
#pragma unroll
            for (int j = 0; j < 8; j++) {
                const int m = m0 + wp * 64 + j * 8 + 2 * (lane & 3);
                const unsigned b  = (unsigned)m / HW;
                const unsigned hw = (unsigned)m - b * HW;
                float v0 = acc[nf][j][half * 2 + 0] * s + t;
                float v1 = acc[nf][j][half * 2 + 1] * s + t;
                v0 = 0.5f * v0 * (1.0f + erff(v0 * 0.70710678118654752440f));
                v1 = 0.5f * v1 * (1.0f + erff(v1 * 0.70710678118654752440f));
                float2 r2 = make_float2(v0, v1);
                *reinterpret_cast<float2*>(
                    out + ((size_t)b * NOUT + n) * HW + hw) = r2;
            }
        }
    }
}

// ---------------- launch ----------------
extern "C" void kernel_launch(void* const* d_in, const int* in_sizes, int n_in,
                              void* d_out, int out_size) {
    const float* x        = (const float*)d_in[0];
    const float* conv_w   = (const float*)d_in[1];
    const float* conv_b   = (const float*)d_in[2];
    const float* bn_scale = (const float*)d_in[3];
    const float* bn_bias  = (const float*)d_in[4];
    const float* bn_mean  = (const float*)d_in[5];
    const float* bn_var   = (const float*)d_in[6];
    float* out = (float*)d_out;

    cudaFuncSetAttribute(gemm_kernel,
                         cudaFuncAttributeMaxDynamicSharedMemorySize, SMEM_BYTES);

    xj_kernel<<<B_ * C_, 256>>>(x);
    wround_kernel<<<(NOUT * K0 + 255) / 256, 256>>>(conv_w);
    gemm_kernel<<<dim3(NOUT / NT, M_ / MT), 256, SMEM_BYTES>>>(
        x, conv_b, bn_scale, bn_bias, bn_mean, bn_var, out);
}

// round 3
// speedup vs baseline: 1.1759x; 1.1759x over previous
#include <cuda_runtime.h>
#include <cstdint>

#define DI __device__ __forceinline__

// ---------------- problem constants ----------------
constexpr int B_   = 16;
constexpr int C_   = 384;
constexpr int H_   = 56;
constexpr int W_   = 56;
constexpr int HW   = H_ * W_;          // 3136
constexpr int M_   = B_ * HW;          // 50176 (pixels)
constexpr int K0   = 2 * C_;           // 768
constexpr int NOUT = 384;

// ---------------- device scratch ----------------
__device__ __align__(256) float g_xj[(size_t)B_ * C_ * HW];   // 77 MB
__device__ __align__(256) float g_Wr[NOUT * K0];              // tf32-rounded weights

// ---------------- PTX helpers ----------------
DI uint32_t smem_u32(const void* p) {
    uint32_t a;
    asm("{ .reg .u64 t; cvta.to.shared.u64 t, %1; cvt.u32.u64 %0, t; }"
        : "=r"(a) : "l"(p));
    return a;
}

DI uint32_t f2tf32(float f) {
    uint32_t r;
    asm("cvt.rna.tf32.f32 %0, %1;" : "=r"(r) : "f"(f));
    return r;
}

#define CP_ASYNC16(smem, gptr) \
    asm volatile("cp.async.cg.shared.global [%0], [%1], 16;" :: "r"(smem), "l"(gptr))
#define CP_COMMIT() asm volatile("cp.async.commit_group;")
#define CP_WAIT1()  asm volatile("cp.async.wait_group 1;")
#define CP_WAIT0()  asm volatile("cp.async.wait_group 0;")

DI void ldsm_x4(uint32_t* r, uint32_t addr) {
    asm volatile("ldmatrix.sync.aligned.m8n8.x4.shared.b16 {%0,%1,%2,%3}, [%4];"
                 : "=r"(r[0]), "=r"(r[1]), "=r"(r[2]), "=r"(r[3]) : "r"(addr));
}

DI float lds_f32(uint32_t addr) {
    float f;
    asm volatile("ld.shared.f32 %0, [%1];" : "=f"(f) : "r"(addr));
    return f;
}

// D[16 n_out][8 pix] += A[16 n_out][8 k] * B[8 k][8 pix]
DI void mma_tf32(float* d, const uint32_t* a, uint32_t b0, uint32_t b1) {
    asm volatile(
        "mma.sync.aligned.m16n8k8.row.col.f32.tf32.tf32.f32 "
        "{%0,%1,%2,%3},{%4,%5,%6,%7},{%8,%9},{%0,%1,%2,%3};"
        : "+f"(d[0]), "+f"(d[1]), "+f"(d[2]), "+f"(d[3])
        : "r"(a[0]), "r"(a[1]), "r"(a[2]), "r"(a[3]), "r"(b0), "r"(b1));
}

// ---------------- kernel 1: round W to tf32 (RN) ----------------
__global__ void wround_kernel(const float* __restrict__ w) {
    const int i = blockIdx.x * blockDim.x + threadIdx.x;
    if (i < NOUT * K0) g_Wr[i] = __uint_as_float(f2tf32(w[i]));
}

// ---------------- kernel 2: x_j (log-shift-max), padded-smem version ----------
// tile: logical [118 rows][118 cols], row stride 120 words. Cell (r,c) holds
// x[(r-31) mod 56][(c-31) mod 56]. Only cross regions are filled/used.
constexpr int TSTR = 120;
constexpr int XJ_SMEM = 118 * TSTR * 4;   // 56640 B (dynamic)

__global__ void __launch_bounds__(448) xj_kernel(const float* __restrict__ x) {
    extern __shared__ float t[];
    const int img = blockIdx.x;                 // b*C + c
    const float* src = x + (size_t)img * HW;
    const int w  = threadIdx.x;                 // 0..63 (>=56 idle)
    const int ty = threadIdx.y;                 // 0..6
    const int hb = ty * 8;

    // center fill
    if (w < W_) {
#pragma unroll
        for (int j = 0; j < 8; j++)
            t[(31 + hb + j) * TSTR + 31 + w] = src[(hb + j) * W_ + w];
    }
    __syncthreads();

    // vertical wings (center cols): rows 0..30 <- +56 ; rows 87..117 <- -56
    if (w < W_) {
#pragma unroll
        for (int r = ty; r < 31; r += 7) {
            t[r * TSTR + 31 + w]        = t[(r + 56) * TSTR + 31 + w];
            t[(r + 87) * TSTR + 31 + w] = t[(r + 31) * TSTR + 31 + w];
        }
    }
    // horizontal wings (center rows): cols 0..30 <- +56 ; cols 87..117 <- -56
    if (w < 31) {
#pragma unroll
        for (int r = 31 + ty; r < 87; r += 7) {
            t[r * TSTR + w]      = t[r * TSTR + w + 56];
            t[r * TSTR + 87 + w] = t[r * TSTR + 31 + w];
        }
    }
    __syncthreads();

    if (w >= W_) return;

    const float* bp = &t[(31 + hb) * TSTR + 31 + w];
    // column strip registers c[i] = row (hb - 3 + i)
    float c[14];
#pragma unroll
    for (int i = 0; i < 14; i++) c[i] = bp[(i - 3) * TSTR];

    float* dst = g_xj + (size_t)img * HW + hb * W_ + w;
#pragma unroll
    for (int j = 0; j < 8; j++) {
        const float* p = bp + j * TSTR;
        const float v = c[j + 3];
        float m = fminf(c[j + 2], c[j + 4]);                     // vert s=1
        m = fminf(m, fminf(c[j], c[j + 6]));                     // vert s=3
        m = fminf(m, fminf(p[-7 * TSTR],  p[7 * TSTR]));         // vert s=7
        m = fminf(m, fminf(p[-15 * TSTR], p[15 * TSTR]));        // vert s=15
        m = fminf(m, fminf(p[-31 * TSTR], p[31 * TSTR]));        // vert s=31
        m = fminf(m, fminf(p[-1],  p[1]));                       // horiz
        m = fminf(m, fminf(p[-3],  p[3]));
        m = fminf(m, fminf(p[-7],  p[7]));
        m = fminf(m, fminf(p[-15], p[15]));
        m = fminf(m, fminf(p[-31], p[31]));
        dst[j * W_] = fmaxf(0.f, v - m);
    }
}

// ---------------- kernel 3: tf32 mma.sync GEMM + BN + GELU ----------------
// D[n_out][pix] ; CTA tile: 128 n_out x 128 pix ; K chunks of 32.
// Warp tile: 64 n x 32 m  (4 MMAs share each B operand pair).
constexpr int MT  = 128;   // pixels
constexpr int NT  = 128;   // n_out
constexpr int KT  = 32;
constexpr int NCH = K0 / KT;   // 24
constexpr int SXS = 136;       // sX row stride (words)
constexpr int SWS = 36;        // sW row stride (words)
constexpr int SX_STAGE = KT * SXS;   // 4352 words
constexpr int SW_STAGE = NT * SWS;   // 4608 words
constexpr int SMEM_BYTES = (2 * SX_STAGE + 2 * SW_STAGE) * 4;  // 71680

__global__ void __launch_bounds__(256, 2) gemm_kernel(
    const float* __restrict__ x,
    const float* __restrict__ conv_b,
    const float* __restrict__ bn_scale, const float* __restrict__ bn_bias,
    const float* __restrict__ bn_mean,  const float* __restrict__ bn_var,
    float* __restrict__ out)
{
    extern __shared__ float sm[];
    float* sX = sm;                     // [2][KT][SXS]
    float* sW = sm + 2 * SX_STAGE;      // [2][NT][SWS]
    __shared__ float s_s[NT], s_t[NT];

    const int tid  = threadIdx.x;
    const int lane = tid & 31;
    const int wid  = tid >> 5;
    const int wn   = wid & 1;           // n_out warp row (2 x 64)
    const int wp   = wid >> 1;          // pixel warp col (4 x 32)
    const int n0   = blockIdx.x * NT;
    const int m0   = blockIdx.y * MT;

    // fold conv bias + BN:  y = dot * s + t
    if (tid < NT) {
        const int n = n0 + tid;
        const float inv = rsqrtf(bn_var[n] + 1e-5f);
        const float s = inv * bn_scale[n];
        s_s[tid] = s;
        s_t[tid] = (conv_b[n] - bn_mean[n]) * s + bn_bias[n];
    }

    const uint32_t sxB = smem_u32(sX);
    const uint32_t swB = smem_u32(sW);

    // ---- staging ----
    auto load_chunk = [&](int ch, int st) {
        const int kc = ch * KT;
        const uint32_t xb = sxB + (uint32_t)st * SX_STAGE * 4;
        const uint32_t wb = swB + (uint32_t)st * SW_STAGE * 4;
        // sX: 32 k-rows x 128 floats ; 1024 float4s
#pragma unroll
        for (int i = 0; i < 4; i++) {
            const int idx = tid + 256 * i;
            const int k   = idx >> 5;          // 0..31
            const int mv  = idx & 31;          // float4 index along m
            const int m   = m0 + 4 * mv;
            const unsigned b  = (unsigned)m / HW;
            const unsigned hw = (unsigned)m - b * HW;
            const int kg = kc + k;
            const float* src = (kg < C_)
                ? (x    + ((size_t)(b * C_ + kg)      ) * HW + hw)
                : (g_xj + ((size_t)(b * C_ + kg - C_) ) * HW + hw);
            CP_ASYNC16(xb + (uint32_t)(k * SXS + 4 * mv) * 4, src);
        }
        // sW: 128 n-rows x 32 floats ; 1024 float4s
#pragma unroll
        for (int i = 0; i < 4; i++) {
            const int idx = tid + 256 * i;
            const int n   = idx >> 3;          // 0..127
            const int kv  = idx & 7;
            const float* src = g_Wr + (size_t)(n0 + n) * K0 + kc + 4 * kv;
            CP_ASYNC16(wb + (uint32_t)(n * SWS + 4 * kv) * 4, src);
        }
    };

    float acc[4][4][4];
#pragma unroll
    for (int a = 0; a < 4; a++)
#pragma unroll
        for (int j = 0; j < 4; j++)
#pragma unroll
            for (int q = 0; q < 4; q++) acc[a][j][q] = 0.f;

    load_chunk(0, 0);
    CP_COMMIT();

#pragma unroll 1
    for (int ch = 0; ch < NCH; ch++) {
        if (ch + 1 < NCH) {
            load_chunk(ch + 1, (ch + 1) & 1);
            CP_COMMIT();
            CP_WAIT1();
        } else {
            CP_WAIT0();
        }
        __syncthreads();

        const int st = ch & 1;
        const uint32_t xb = sxB + (uint32_t)st * SX_STAGE * 4;
        const uint32_t wb = swB + (uint32_t)st * SW_STAGE * 4;

        const int jrow = (lane & 7) + ((lane >> 3) & 1) * 8;   // row within 16
        const int kcol = ((lane >> 3) >> 1) * 4;               // word offset 0 or 4

#pragma unroll
        for (int ks = 0; ks < 4; ks++) {
            const int k8 = ks * 8;
            uint32_t afr[4][4];
#pragma unroll
            for (int nf = 0; nf < 4; nf++) {
                const int row = wn * 64 + nf * 16 + jrow;
                ldsm_x4(afr[nf], wb + (uint32_t)(row * SWS + k8 + kcol) * 4);
            }
            const uint32_t b0base = xb + (uint32_t)((k8 + (lane & 3)) * SXS
                                                    + wp * 32 + (lane >> 2)) * 4;
#pragma unroll
            for (int j = 0; j < 4; j++) {
                const uint32_t a0 = b0base + (uint32_t)(j * 8) * 4;
                const uint32_t b0 = f2tf32(lds_f32(a0));
                const uint32_t b1 = f2tf32(lds_f32(a0 + (uint32_t)(4 * SXS) * 4));
                mma_tf32(acc[0][j], afr[0], b0, b1);
                mma_tf32(acc[1][j], afr[1], b0, b1);
                mma_tf32(acc[2][j], afr[2], b0, b1);
                mma_tf32(acc[3][j], afr[3], b0, b1);
            }
        }
        __syncthreads();
    }

    // ---- epilogue: BN + exact GELU, write out[b][n][hw] ----
#pragma unroll
    for (int nf = 0; nf < 4; nf++) {
#pragma unroll
        for (int half = 0; half < 2; half++) {
            const int ntile = wn * 64 + nf * 16 + (lane >> 2) + half * 8;
            const int n = n0 + ntile;
            const float s = s_s[ntile];
            const float t = s_t[ntile];
#pragma unroll
            for (int j = 0; j < 4; j++) {
                const int m = m0 + wp * 32 + j * 8 + 2 * (lane & 3);
                const unsigned b  = (unsigned)m / HW;
                const unsigned hw = (unsigned)m - b * HW;
                float v0 = acc[nf][j][half * 2 + 0] * s + t;
                float v1 = acc[nf][j][half * 2 + 1] * s + t;
                v0 = 0.5f * v0 * (1.0f + erff(v0 * 0.70710678118654752440f));
                v1 = 0.5f * v1 * (1.0f + erff(v1 * 0.70710678118654752440f));
                float2 r2 = make_float2(v0, v1);
                *reinterpret_cast<float2*>(
                    out + ((size_t)b * NOUT + n) * HW + hw) = r2;
            }
        }
    }
}

// ---------------- launch ----------------
extern "C" void kernel_launch(void* const* d_in, const int* in_sizes, int n_in,
                              void* d_out, int out_size) {
    const float* x        = (const float*)d_in[0];
    const float* conv_w   = (const float*)d_in[1];
    const float* conv_b   = (const float*)d_in[2];
    const float* bn_scale = (const float*)d_in[3];
    const float* bn_bias  = (const float*)d_in[4];
    const float* bn_mean  = (const float*)d_in[5];
    const float* bn_var   = (const float*)d_in[6];
    float* out = (float*)d_out;

    cudaFuncSetAttribute(xj_kernel,
                         cudaFuncAttributeMaxDynamicSharedMemorySize, XJ_SMEM);
    cudaFuncSetAttribute(gemm_kernel,
                         cudaFuncAttributeMaxDynamicSharedMemorySize, SMEM_BYTES);

    wround_kernel<<<(NOUT * K0 + 255) / 256, 256>>>(conv_w);
    xj_kernel<<<B_ * C_, dim3(64, 7), XJ_SMEM>>>(x);
    gemm_kernel<<<dim3(NOUT / NT, M_ / MT), 256, SMEM_BYTES>>>(
        x, conv_b, bn_scale, bn_bias, bn_mean, bn_var, out);
}

// round 4
// speedup vs baseline: 1.5854x; 1.3482x over previous
#include <cuda_runtime.h>
#include <cuda_fp16.h>
#include <cstdint>

#define DI __device__ __forceinline__

// ---------------- problem constants ----------------
constexpr int B_   = 16;
constexpr int C_   = 384;
constexpr int H_   = 56;
constexpr int W_   = 56;
constexpr int HW   = H_ * W_;          // 3136
constexpr int M_   = B_ * HW;          // 50176 (pixels)
constexpr int K0   = 2 * C_;           // 768
constexpr int K2T  = K0 / 2;           // 384 packed k-pairs
constexpr int NOUT = 384;

// ---------------- device scratch ----------------
// Xp: packed fp16 pairs, word (k2, m): {fp16(val[2*k2]), fp16(val[2*k2+1])}
// layout [b][k2][hw] as uint32 words; k2 in 0..191 -> x channel pairs,
// k2 in 192..383 -> xj channel pairs.
__device__ __align__(256) uint32_t g_Xp[(size_t)B_ * K2T * HW];   // 77 MB
__device__ __align__(256) __half   g_Wh[NOUT * K0];               // fp16 W [n][k]

// ---------------- PTX helpers ----------------
DI uint32_t smem_u32(const void* p) {
    uint32_t a;
    asm("{ .reg .u64 t; cvta.to.shared.u64 t, %1; cvt.u32.u64 %0, t; }"
        : "=r"(a) : "l"(p));
    return a;
}

#define CP_ASYNC16(smem, gptr) \
    asm volatile("cp.async.cg.shared.global [%0], [%1], 16;" :: "r"(smem), "l"(gptr))
#define CP_COMMIT() asm volatile("cp.async.commit_group;")
#define CP_WAIT1()  asm volatile("cp.async.wait_group 1;")
#define CP_WAIT0()  asm volatile("cp.async.wait_group 0;")

DI void ldsm_x4(uint32_t* r, uint32_t addr) {
    asm volatile("ldmatrix.sync.aligned.m8n8.x4.shared.b16 {%0,%1,%2,%3}, [%4];"
                 : "=r"(r[0]), "=r"(r[1]), "=r"(r[2]), "=r"(r[3]) : "r"(addr));
}

DI uint32_t lds_u32(uint32_t addr) {
    uint32_t v;
    asm volatile("ld.shared.b32 %0, [%1];" : "=r"(v) : "r"(addr));
    return v;
}

// D[16 n][8 m] += A[16 n][16 k](f16) * B[16 k][8 m](f16), f32 accum
DI void mma_f16(float* d, const uint32_t* a, uint32_t b0, uint32_t b1) {
    asm volatile(
        "mma.sync.aligned.m16n8k16.row.col.f32.f16.f16.f32 "
        "{%0,%1,%2,%3},{%4,%5,%6,%7},{%8,%9},{%0,%1,%2,%3};"
        : "+f"(d[0]), "+f"(d[1]), "+f"(d[2]), "+f"(d[3])
        : "r"(a[0]), "r"(a[1]), "r"(a[2]), "r"(a[3]), "r"(b0), "r"(b1));
}

DI uint32_t pack_h2(float a, float b) {
    __half2 h = __halves2half2(__float2half_rn(a), __float2half_rn(b));
    return *reinterpret_cast<uint32_t*>(&h);
}

// ---------------- kernel 1: xjpack (log-shift-max + fp16 pair pack) ---------
// One block per (b, channel-pair). Two padded tiles in smem:
// logical [118 rows][118 cols], row stride 120 words; cell (r,c) holds
// img[(r-31) mod 56][(c-31) mod 56].
constexpr int TSTR = 120;
constexpr int TILE_WORDS = 118 * TSTR;              // 14160
constexpr int XJ_SMEM = 2 * TILE_WORDS * 4;         // 113280 B

__global__ void __launch_bounds__(448) xjpack_kernel(const float* __restrict__ x) {
    extern __shared__ float t[];
    float* t0 = t;
    float* t1 = t + TILE_WORDS;

    const int c2 = blockIdx.x % (C_ / 2);
    const int b  = blockIdx.x / (C_ / 2);
    const float* src0 = x + ((size_t)b * C_ + 2 * c2    ) * HW;
    const float* src1 = x + ((size_t)b * C_ + 2 * c2 + 1) * HW;

    const int w  = threadIdx.x;                 // 0..63 (>=56 idle)
    const int ty = threadIdx.y;                 // 0..6
    const int hb = ty * 8;

    // center fill
    if (w < W_) {
#pragma unroll
        for (int j = 0; j < 8; j++) {
            t0[(31 + hb + j) * TSTR + 31 + w] = src0[(hb + j) * W_ + w];
            t1[(31 + hb + j) * TSTR + 31 + w] = src1[(hb + j) * W_ + w];
        }
    }
    __syncthreads();

    // vertical wings (center cols)
    if (w < W_) {
#pragma unroll
        for (int r = ty; r < 31; r += 7) {
            t0[r * TSTR + 31 + w]        = t0[(r + 56) * TSTR + 31 + w];
            t0[(r + 87) * TSTR + 31 + w] = t0[(r + 31) * TSTR + 31 + w];
            t1[r * TSTR + 31 + w]        = t1[(r + 56) * TSTR + 31 + w];
            t1[(r + 87) * TSTR + 31 + w] = t1[(r + 31) * TSTR + 31 + w];
        }
    }
    // horizontal wings (center rows)
    if (w < 31) {
#pragma unroll
        for (int r = 31 + ty; r < 87; r += 7) {
            t0[r * TSTR + w]      = t0[r * TSTR + w + 56];
            t0[r * TSTR + 87 + w] = t0[r * TSTR + 31 + w];
            t1[r * TSTR + w]      = t1[r * TSTR + w + 56];
            t1[r * TSTR + 87 + w] = t1[r * TSTR + 31 + w];
        }
    }
    __syncthreads();

    if (w >= W_) return;

    const float* bp0 = &t0[(31 + hb) * TSTR + 31 + w];
    const float* bp1 = &t1[(31 + hb) * TSTR + 31 + w];
    float c0[14], c1[14];
#pragma unroll
    for (int i = 0; i < 14; i++) {
        c0[i] = bp0[(i - 3) * TSTR];
        c1[i] = bp1[(i - 3) * TSTR];
    }

    uint32_t* dx = g_Xp + ((size_t)b * K2T + c2)       * HW + hb * W_ + w;
    uint32_t* dj = g_Xp + ((size_t)b * K2T + 192 + c2) * HW + hb * W_ + w;

#pragma unroll
    for (int j = 0; j < 8; j++) {
        const float* p0 = bp0 + j * TSTR;
        const float* p1 = bp1 + j * TSTR;
        const float v0 = c0[j + 3];
        const float v1 = c1[j + 3];

        float m0 = fminf(c0[j + 2], c0[j + 4]);
        m0 = fminf(m0, fminf(c0[j], c0[j + 6]));
        m0 = fminf(m0, fminf(p0[-7 * TSTR],  p0[7 * TSTR]));
        m0 = fminf(m0, fminf(p0[-15 * TSTR], p0[15 * TSTR]));
        m0 = fminf(m0, fminf(p0[-31 * TSTR], p0[31 * TSTR]));
        m0 = fminf(m0, fminf(p0[-1],  p0[1]));
        m0 = fminf(m0, fminf(p0[-3],  p0[3]));
        m0 = fminf(m0, fminf(p0[-7],  p0[7]));
        m0 = fminf(m0, fminf(p0[-15], p0[15]));
        m0 = fminf(m0, fminf(p0[-31], p0[31]));

        float m1 = fminf(c1[j + 2], c1[j + 4]);
        m1 = fminf(m1, fminf(c1[j], c1[j + 6]));
        m1 = fminf(m1, fminf(p1[-7 * TSTR],  p1[7 * TSTR]));
        m1 = fminf(m1, fminf(p1[-15 * TSTR], p1[15 * TSTR]));
        m1 = fminf(m1, fminf(p1[-31 * TSTR], p1[31 * TSTR]));
        m1 = fminf(m1, fminf(p1[-1],  p1[1]));
        m1 = fminf(m1, fminf(p1[-3],  p1[3]));
        m1 = fminf(m1, fminf(p1[-7],  p1[7]));
        m1 = fminf(m1, fminf(p1[-15], p1[15]));
        m1 = fminf(m1, fminf(p1[-31], p1[31]));

        dx[j * W_] = pack_h2(v0, v1);
        dj[j * W_] = pack_h2(fmaxf(0.f, v0 - m0), fmaxf(0.f, v1 - m1));
    }
}

// ---------------- kernel 2: W -> fp16 [n][k] ----------------
__global__ void whalf_kernel(const float* __restrict__ w) {
    const int i = blockIdx.x * blockDim.x + threadIdx.x;
    if (i < NOUT * K0) g_Wh[i] = __float2half_rn(w[i]);
}

// ---------------- kernel 3: fp16 mma.sync GEMM + BN + GELU ----------------
// D[n_out][pix]; CTA tile 128n x 128m; K chunks of 32 (16 k2 words).
// Warp tile: 64n x 32m. mma m16n8k16: A=W fp16 (ldmatrix), B=Xp packed words.
constexpr int MT  = 128;
constexpr int NT  = 128;
constexpr int KT  = 32;          // k per chunk
constexpr int NCH = K0 / KT;     // 24
constexpr int SXS = 136;         // sX row stride (words), 16 rows/stage
constexpr int SWSH = 40;         // sW row stride (halfs) -> 80B, ldsm conflict-free
constexpr int SX_STAGE_W = 16 * SXS;          // words
constexpr int SW_STAGE_H = NT * SWSH;         // halfs
constexpr int SMEM_BYTES = 2 * SX_STAGE_W * 4 + 2 * SW_STAGE_H * 2;  // 37888

__global__ void __launch_bounds__(256, 2) gemm_kernel(
    const float* __restrict__ conv_b,
    const float* __restrict__ bn_scale, const float* __restrict__ bn_bias,
    const float* __restrict__ bn_mean,  const float* __restrict__ bn_var,
    float* __restrict__ out)
{
    extern __shared__ uint32_t smw[];
    uint32_t* sX = smw;                         // [2][16][SXS] words
    __half*   sW = (__half*)(smw + 2 * SX_STAGE_W);  // [2][NT][SWSH] halfs
    __shared__ float s_s[NT], s_t[NT];

    const int tid  = threadIdx.x;
    const int lane = tid & 31;
    const int wid  = tid >> 5;
    const int wn   = wid & 1;           // 2 x 64 n
    const int wp   = wid >> 1;          // 4 x 32 m
    const int n0   = blockIdx.x * NT;
    const int m0   = blockIdx.y * MT;

    if (tid < NT) {
        const int n = n0 + tid;
        const float inv = rsqrtf(bn_var[n] + 1e-5f);
        const float s = inv * bn_scale[n];
        s_s[tid] = s;
        s_t[tid] = (conv_b[n] - bn_mean[n]) * s + bn_bias[n];
    }

    const uint32_t sxB = smem_u32(sX);
    const uint32_t swB = smem_u32(sW);

    auto load_chunk = [&](int ch, int st) {
        const int kc2 = ch * (KT / 2);          // k2 offset
        const uint32_t xb = sxB + (uint32_t)st * SX_STAGE_W * 4;
        const uint32_t wb = swB + (uint32_t)st * SW_STAGE_H * 2;
        // sX: 16 k2-rows x 128 words ; 512 x 16B
#pragma unroll
        for (int i = 0; i < 2; i++) {
            const int idx = tid + 256 * i;
            const int k2  = idx >> 5;           // 0..15
            const int mv  = idx & 31;           // 16B unit (4 m)
            const int m   = m0 + 4 * mv;
            const unsigned b  = (unsigned)m / HW;
            const unsigned hw = (unsigned)m - b * HW;
            const uint32_t* src = g_Xp + ((size_t)b * K2T + kc2 + k2) * HW + hw;
            CP_ASYNC16(xb + (uint32_t)(k2 * SXS + 4 * mv) * 4, src);
        }
        // sW: 128 n-rows x 32 halfs ; 512 x 16B
#pragma unroll
        for (int i = 0; i < 2; i++) {
            const int idx = tid + 256 * i;
            const int n   = idx >> 2;           // 0..127
            const int kv  = idx & 3;            // 8-half unit
            const __half* src = g_Wh + (size_t)(n0 + n) * K0 + ch * KT + 8 * kv;
            CP_ASYNC16(wb + (uint32_t)(n * SWSH + 8 * kv) * 2, src);
        }
    };

    float acc[4][4][4];
#pragma unroll
    for (int a = 0; a < 4; a++)
#pragma unroll
        for (int j = 0; j < 4; j++)
#pragma unroll
            for (int q = 0; q < 4; q++) acc[a][j][q] = 0.f;

    load_chunk(0, 0);
    CP_COMMIT();

    // ldmatrix per-lane row/col pieces (A = W tile, 16x16 f16)
    const int jrow = (lane & 7) + ((lane >> 3) & 1) * 8;
    const int kcol = (lane >> 4) * 8;           // half offset 0 or 8

#pragma unroll 1
    for (int ch = 0; ch < NCH; ch++) {
        if (ch + 1 < NCH) {
            load_chunk(ch + 1, (ch + 1) & 1);
            CP_COMMIT();
            CP_WAIT1();
        } else {
            CP_WAIT0();
        }
        __syncthreads();

        const int st = ch & 1;
        const uint32_t xb = sxB + (uint32_t)st * SX_STAGE_W * 4;
        const uint32_t wb = swB + (uint32_t)st * SW_STAGE_H * 2;

#pragma unroll
        for (int ks = 0; ks < 2; ks++) {        // two k16 steps
            uint32_t afr[4][4];
#pragma unroll
            for (int nf = 0; nf < 4; nf++) {
                const int row = wn * 64 + nf * 16 + jrow;
                ldsm_x4(afr[nf], wb + (uint32_t)(row * SWSH + ks * 16 + kcol) * 2);
            }
            // B operand: word {k=2*k2, 2*k2+1} at m
            const uint32_t bbase = xb + (uint32_t)((ks * 8 + (lane & 3)) * SXS
                                                   + wp * 32 + (lane >> 2)) * 4;
#pragma unroll
            for (int j = 0; j < 4; j++) {
                const uint32_t a0 = bbase + (uint32_t)(j * 8) * 4;
                const uint32_t b0 = lds_u32(a0);
                const uint32_t b1 = lds_u32(a0 + (uint32_t)(4 * SXS) * 4);
                mma_f16(acc[0][j], afr[0], b0, b1);
                mma_f16(acc[1][j], afr[1], b0, b1);
                mma_f16(acc[2][j], afr[2], b0, b1);
                mma_f16(acc[3][j], afr[3], b0, b1);
            }
        }
        __syncthreads();
    }

    // ---- epilogue: BN + exact GELU ----
#pragma unroll
    for (int nf = 0; nf < 4; nf++) {
#pragma unroll
        for (int half = 0; half < 2; half++) {
            const int ntile = wn * 64 + nf * 16 + (lane >> 2) + half * 8;
            const int n = n0 + ntile;
            const float s = s_s[ntile];
            const float t = s_t[ntile];
#pragma unroll
            for (int j = 0; j < 4; j++) {
                const int m = m0 + wp * 32 + j * 8 + 2 * (lane & 3);
                const unsigned b  = (unsigned)m / HW;
                const unsigned hw = (unsigned)m - b * HW;
                float v0 = acc[nf][j][half * 2 + 0] * s + t;
                float v1 = acc[nf][j][half * 2 + 1] * s + t;
                v0 = 0.5f * v0 * (1.0f + erff(v0 * 0.70710678118654752440f));
                v1 = 0.5f * v1 * (1.0f + erff(v1 * 0.70710678118654752440f));
                *reinterpret_cast<float2*>(
                    out + ((size_t)b * NOUT + n) * HW + hw) = make_float2(v0, v1);
            }
        }
    }
}

// ---------------- launch ----------------
extern "C" void kernel_launch(void* const* d_in, const int* in_sizes, int n_in,
                              void* d_out, int out_size) {
    const float* x        = (const float*)d_in[0];
    const float* conv_w   = (const float*)d_in[1];
    const float* conv_b   = (const float*)d_in[2];
    const float* bn_scale = (const float*)d_in[3];
    const float* bn_bias  = (const float*)d_in[4];
    const float* bn_mean  = (const float*)d_in[5];
    const float* bn_var   = (const float*)d_in[6];
    float* out = (float*)d_out;

    cudaFuncSetAttribute(xjpack_kernel,
                         cudaFuncAttributeMaxDynamicSharedMemorySize, XJ_SMEM);
    cudaFuncSetAttribute(gemm_kernel,
                         cudaFuncAttributeMaxDynamicSharedMemorySize, SMEM_BYTES);

    xjpack_kernel<<<B_ * (C_ / 2), dim3(64, 7), XJ_SMEM>>>(x);
    whalf_kernel<<<(NOUT * K0 + 255) / 256, 256>>>(conv_w);
    gemm_kernel<<<dim3(NOUT / NT, M_ / MT), 256, SMEM_BYTES>>>(
        conv_b, bn_scale, bn_bias, bn_mean, bn_var, out);
}

// round 5
// speedup vs baseline: 1.8354x; 1.1577x over previous
#include <cuda_runtime.h>
#include <cuda_fp16.h>
#include <cstdint>

#define DI __device__ __forceinline__

// ---------------- problem constants ----------------
constexpr int B_   = 16;
constexpr int C_   = 384;
constexpr int H_   = 56;
constexpr int W_   = 56;
constexpr int HW   = H_ * W_;          // 3136
constexpr int M_   = B_ * HW;          // 50176 (pixels)
constexpr int K0   = 2 * C_;           // 768
constexpr int K2T  = K0 / 2;           // 384 packed k-pairs
constexpr int NOUT = 384;

// ---------------- device scratch ----------------
// Xp: packed fp16 pairs, word (k2, m): {fp16(val[2*k2]), fp16(val[2*k2+1])}
// layout [b][k2][hw]; k2 0..191 -> x channel pairs, 192..383 -> xj pairs.
__device__ __align__(256) uint32_t g_Xp[(size_t)B_ * K2T * HW];   // 77 MB
__device__ __align__(256) __half   g_Wh[NOUT * K0];               // fp16 W [n][k]

// ---------------- PTX helpers ----------------
DI uint32_t smem_u32(const void* p) {
    uint32_t a;
    asm("{ .reg .u64 t; cvta.to.shared.u64 t, %1; cvt.u32.u64 %0, t; }"
        : "=r"(a) : "l"(p));
    return a;
}

#define CP_ASYNC16(smem, gptr) \
    asm volatile("cp.async.cg.shared.global [%0], [%1], 16;" :: "r"(smem), "l"(gptr))
#define CP_COMMIT() asm volatile("cp.async.commit_group;")
#define CP_WAIT1()  asm volatile("cp.async.wait_group 1;")
#define CP_WAIT0()  asm volatile("cp.async.wait_group 0;")

DI void ldsm_x4(uint32_t* r, uint32_t addr) {
    asm volatile("ldmatrix.sync.aligned.m8n8.x4.shared.b16 {%0,%1,%2,%3}, [%4];"
                 : "=r"(r[0]), "=r"(r[1]), "=r"(r[2]), "=r"(r[3]) : "r"(addr));
}

DI uint32_t lds_u32(uint32_t addr) {
    uint32_t v;
    asm volatile("ld.shared.b32 %0, [%1];" : "=r"(v) : "r"(addr));
    return v;
}

// D[16 n][8 m] += A[16 n][16 k](f16) * B[16 k][8 m](f16), f32 accum
DI void mma_f16(float* d, const uint32_t* a, uint32_t b0, uint32_t b1) {
    asm volatile(
        "mma.sync.aligned.m16n8k16.row.col.f32.f16.f16.f32 "
        "{%0,%1,%2,%3},{%4,%5,%6,%7},{%8,%9},{%0,%1,%2,%3};"
        : "+f"(d[0]), "+f"(d[1]), "+f"(d[2]), "+f"(d[3])
        : "r"(a[0]), "r"(a[1]), "r"(a[2]), "r"(a[3]), "r"(b0), "r"(b1));
}

DI uint32_t pack_h2(float a, float b) {
    __half2 h = __halves2half2(__float2half_rn(a), __float2half_rn(b));
    return *reinterpret_cast<uint32_t*>(&h);
}

DI __half2 u2h(uint32_t u) { return *reinterpret_cast<__half2*>(&u); }
DI uint32_t h2u(__half2 h) { return *reinterpret_cast<uint32_t*>(&h); }

// ---------------- kernel 1: xjpack (half2 tile, log-shift-max + pack) -------
// One block per (b, channel-pair). Single packed half2 tile:
// logical [118 rows][118 cols], row stride 120 words; cell (r,c) holds
// {fp16 img0, fp16 img1}[(r-31) mod 56][(c-31) mod 56].
constexpr int TSTR = 120;
constexpr int XJ_SMEM = 118 * TSTR * 4;             // 56640 B

__global__ void __launch_bounds__(448, 2) xjpack_kernel(const float* __restrict__ x) {
    extern __shared__ uint32_t t[];

    const int c2 = blockIdx.x % (C_ / 2);
    const int b  = blockIdx.x / (C_ / 2);
    const float* src0 = x + ((size_t)b * C_ + 2 * c2    ) * HW;
    const float* src1 = x + ((size_t)b * C_ + 2 * c2 + 1) * HW;

    const int w  = threadIdx.x;                 // 0..63 (>=56 idle)
    const int ty = threadIdx.y;                 // 0..6
    const int hb = ty * 8;

    // center fill (pack both channels into one half2 word)
    if (w < W_) {
#pragma unroll
        for (int j = 0; j < 8; j++)
            t[(31 + hb + j) * TSTR + 31 + w] =
                pack_h2(src0[(hb + j) * W_ + w], src1[(hb + j) * W_ + w]);
    }
    __syncthreads();

    // vertical wings (center cols)
    if (w < W_) {
#pragma unroll
        for (int r = ty; r < 31; r += 7) {
            t[r * TSTR + 31 + w]        = t[(r + 56) * TSTR + 31 + w];
            t[(r + 87) * TSTR + 31 + w] = t[(r + 31) * TSTR + 31 + w];
        }
    }
    // horizontal wings (center rows)
    if (w < 31) {
#pragma unroll
        for (int r = 31 + ty; r < 87; r += 7) {
            t[r * TSTR + w]      = t[r * TSTR + w + 56];
            t[r * TSTR + 87 + w] = t[r * TSTR + 31 + w];
        }
    }
    __syncthreads();

    if (w >= W_) return;

    const uint32_t* bp = &t[(31 + hb) * TSTR + 31 + w];
    // column strip registers: rows hb-3 .. hb+10 (covers vert s=1,3)
    uint32_t c[14];
#pragma unroll
    for (int i = 0; i < 14; i++) c[i] = bp[(i - 3) * TSTR];

    uint32_t* dx = g_Xp + ((size_t)b * K2T + c2)       * HW + hb * W_ + w;
    uint32_t* dj = g_Xp + ((size_t)b * K2T + 192 + c2) * HW + hb * W_ + w;

    const __half2 zero = __half2half2(__float2half(0.f));

#pragma unroll
    for (int j = 0; j < 8; j++) {
        const uint32_t* p = bp + j * TSTR;
        const __half2 v = u2h(c[j + 3]);

        __half2 m = __hmin2(u2h(c[j + 2]), u2h(c[j + 4]));          // vert s=1
        m = __hmin2(m, __hmin2(u2h(c[j]), u2h(c[j + 6])));          // vert s=3
        m = __hmin2(m, __hmin2(u2h(p[-7 * TSTR]),  u2h(p[7 * TSTR])));
        m = __hmin2(m, __hmin2(u2h(p[-15 * TSTR]), u2h(p[15 * TSTR])));
        m = __hmin2(m, __hmin2(u2h(p[-31 * TSTR]), u2h(p[31 * TSTR])));
        m = __hmin2(m, __hmin2(u2h(p[-1]),  u2h(p[1])));            // horiz
        m = __hmin2(m, __hmin2(u2h(p[-3]),  u2h(p[3])));
        m = __hmin2(m, __hmin2(u2h(p[-7]),  u2h(p[7])));
        m = __hmin2(m, __hmin2(u2h(p[-15]), u2h(p[15])));
        m = __hmin2(m, __hmin2(u2h(p[-31]), u2h(p[31])));

        dx[j * W_] = c[j + 3];
        dj[j * W_] = h2u(__hmax2(__hsub2(v, m), zero));
    }
}

// ---------------- kernel 2: W -> fp16 [n][k] ----------------
__global__ void whalf_kernel(const float* __restrict__ w) {
    const int i = blockIdx.x * blockDim.x + threadIdx.x;
    if (i < NOUT * K0) g_Wh[i] = __float2half_rn(w[i]);
}

// ---------------- kernel 3: fp16 mma.sync GEMM + BN + GELU ----------------
// D[n_out][pix]; CTA tile 128n x 128m; K chunks of 32 (16 k2 words).
// Warp tile: 64n x 32m. mma m16n8k16: A=W fp16 (ldmatrix), B=Xp packed words.
constexpr int MT  = 128;
constexpr int NT  = 128;
constexpr int KT  = 32;          // k per chunk
constexpr int NCH = K0 / KT;     // 24
constexpr int SXS = 136;         // sX row stride (words), 16 rows/stage
constexpr int SWSH = 40;         // sW row stride (halfs) -> 80B
constexpr int SX_STAGE_W = 16 * SXS;          // words
constexpr int SW_STAGE_H = NT * SWSH;         // halfs
constexpr int SMEM_BYTES = 2 * SX_STAGE_W * 4 + 2 * SW_STAGE_H * 2;  // 37888

__global__ void __launch_bounds__(256, 2) gemm_kernel(
    const float* __restrict__ conv_b,
    const float* __restrict__ bn_scale, const float* __restrict__ bn_bias,
    const float* __restrict__ bn_mean,  const float* __restrict__ bn_var,
    float* __restrict__ out)
{
    extern __shared__ uint32_t smw[];
    uint32_t* sX = smw;                              // [2][16][SXS] words
    __half*   sW = (__half*)(smw + 2 * SX_STAGE_W);  // [2][NT][SWSH] halfs
    __shared__ float s_s[NT], s_t[NT];

    const int tid  = threadIdx.x;
    const int lane = tid & 31;
    const int wid  = tid >> 5;
    const int wn   = wid & 1;           // 2 x 64 n
    const int wp   = wid >> 1;          // 4 x 32 m
    const int n0   = blockIdx.x * NT;
    const int m0   = blockIdx.y * MT;

    if (tid < NT) {
        const int n = n0 + tid;
        const float inv = rsqrtf(bn_var[n] + 1e-5f);
        const float s = inv * bn_scale[n];
        s_s[tid] = s;
        s_t[tid] = (conv_b[n] - bn_mean[n]) * s + bn_bias[n];
    }

    const uint32_t sxB = smem_u32(sX);
    const uint32_t swB = smem_u32(sW);

    auto load_chunk = [&](int ch, int st) {
        const int kc2 = ch * (KT / 2);          // k2 offset
        const uint32_t xb = sxB + (uint32_t)st * SX_STAGE_W * 4;
        const uint32_t wb = swB + (uint32_t)st * SW_STAGE_H * 2;
#pragma unroll
        for (int i = 0; i < 2; i++) {
            const int idx = tid + 256 * i;
            const int k2  = idx >> 5;           // 0..15
            const int mv  = idx & 31;           // 16B unit (4 m)
            const int m   = m0 + 4 * mv;
            const unsigned b  = (unsigned)m / HW;
            const unsigned hw = (unsigned)m - b * HW;
            const uint32_t* src = g_Xp + ((size_t)b * K2T + kc2 + k2) * HW + hw;
            CP_ASYNC16(xb + (uint32_t)(k2 * SXS + 4 * mv) * 4, src);
        }
#pragma unroll
        for (int i = 0; i < 2; i++) {
            const int idx = tid + 256 * i;
            const int n   = idx >> 2;           // 0..127
            const int kv  = idx & 3;            // 8-half unit
            const __half* src = g_Wh + (size_t)(n0 + n) * K0 + ch * KT + 8 * kv;
            CP_ASYNC16(wb + (uint32_t)(n * SWSH + 8 * kv) * 2, src);
        }
    };

    float acc[4][4][4];
#pragma unroll
    for (int a = 0; a < 4; a++)
#pragma unroll
        for (int j = 0; j < 4; j++)
#pragma unroll
            for (int q = 0; q < 4; q++) acc[a][j][q] = 0.f;

    load_chunk(0, 0);
    CP_COMMIT();

    const int jrow = (lane & 7) + ((lane >> 3) & 1) * 8;
    const int kcol = (lane >> 4) * 8;           // half offset 0 or 8

#pragma unroll 1
    for (int ch = 0; ch < NCH; ch++) {
        if (ch + 1 < NCH) {
            load_chunk(ch + 1, (ch + 1) & 1);
            CP_COMMIT();
            CP_WAIT1();
        } else {
            CP_WAIT0();
        }
        __syncthreads();

        const int st = ch & 1;
        const uint32_t xb = sxB + (uint32_t)st * SX_STAGE_W * 4;
        const uint32_t wb = swB + (uint32_t)st * SW_STAGE_H * 2;

#pragma unroll
        for (int ks = 0; ks < 2; ks++) {        // two k16 steps
            uint32_t afr[4][4];
#pragma unroll
            for (int nf = 0; nf < 4; nf++) {
                const int row = wn * 64 + nf * 16 + jrow;
                ldsm_x4(afr[nf], wb + (uint32_t)(row * SWSH + ks * 16 + kcol) * 2);
            }
            const uint32_t bbase = xb + (uint32_t)((ks * 8 + (lane & 3)) * SXS
                                                   + wp * 32 + (lane >> 2)) * 4;
#pragma unroll
            for (int j = 0; j < 4; j++) {
                const uint32_t a0 = bbase + (uint32_t)(j * 8) * 4;
                const uint32_t b0 = lds_u32(a0);
                const uint32_t b1 = lds_u32(a0 + (uint32_t)(4 * SXS) * 4);
                mma_f16(acc[0][j], afr[0], b0, b1);
                mma_f16(acc[1][j], afr[1], b0, b1);
                mma_f16(acc[2][j], afr[2], b0, b1);
                mma_f16(acc[3][j], afr[3], b0, b1);
            }
        }
        __syncthreads();
    }

    // ---- epilogue: BN + exact GELU ----
#pragma unroll
    for (int nf = 0; nf < 4; nf++) {
#pragma unroll
        for (int half = 0; half < 2; half++) {
            const int ntile = wn * 64 + nf * 16 + (lane >> 2) + half * 8;
            const int n = n0 + ntile;
            const float s = s_s[ntile];
            const float t = s_t[ntile];
#pragma unroll
            for (int j = 0; j < 4; j++) {
                const int m = m0 + wp * 32 + j * 8 + 2 * (lane & 3);
                const unsigned b  = (unsigned)m / HW;
                const unsigned hw = (unsigned)m - b * HW;
                float v0 = acc[nf][j][half * 2 + 0] * s + t;
                float v1 = acc[nf][j][half * 2 + 1] * s + t;
                v0 = 0.5f * v0 * (1.0f + erff(v0 * 0.70710678118654752440f));
                v1 = 0.5f * v1 * (1.0f + erff(v1 * 0.70710678118654752440f));
                *reinterpret_cast<float2*>(
                    out + ((size_t)b * NOUT + n) * HW + hw) = make_float2(v0, v1);
            }
        }
    }
}

// ---------------- launch ----------------
extern "C" void kernel_launch(void* const* d_in, const int* in_sizes, int n_in,
                              void* d_out, int out_size) {
    const float* x        = (const float*)d_in[0];
    const float* conv_w   = (const float*)d_in[1];
    const float* conv_b   = (const float*)d_in[2];
    const float* bn_scale = (const float*)d_in[3];
    const float* bn_bias  = (const float*)d_in[4];
    const float* bn_mean  = (const float*)d_in[5];
    const float* bn_var   = (const float*)d_in[6];
    float* out = (float*)d_out;

    cudaFuncSetAttribute(xjpack_kernel,
                         cudaFuncAttributeMaxDynamicSharedMemorySize, XJ_SMEM);
    cudaFuncSetAttribute(gemm_kernel,
                         cudaFuncAttributeMaxDynamicSharedMemorySize, SMEM_BYTES);

    xjpack_kernel<<<B_ * (C_ / 2), dim3(64, 7), XJ_SMEM>>>(x);
    whalf_kernel<<<(NOUT * K0 + 255) / 256, 256>>>(conv_w);
    gemm_kernel<<<dim3(NOUT / NT, M_ / MT), 256, SMEM_BYTES>>>(
        conv_b, bn_scale, bn_bias, bn_mean, bn_var, out);
}